// round 14
// baseline (speedup 1.0000x reference)
#include <cuda_runtime.h>
#include <cuda_fp16.h>
#include <cuda.h>
#include <cudaTypedefs.h>
#include <cstdint>

// ---------------- problem constants ----------------
constexpr int kM = 4096, kK = 4096, kN = 14336;
constexpr int TM = 128, TN = 256, TK = 64;
constexpr int KITERS = kK / TK;            // 64
constexpr int NTM = kM / TM;               // 32 (power of 2)
constexpr int NTN = kN / TN;               // 56
constexpr int NTILES = NTM * NTN;          // 1792
constexpr int GRID = 148;                  // persistent, 1 CTA/SM, dynamic stealing
constexpr int STAGES = 3;
constexpr uint32_t STAGE_A = TM * TK * 2;          // 16384 B
constexpr uint32_t STAGE_B = TN * TK * 2;          // 32768 B
constexpr uint32_t STAGE_BYTES = STAGE_A + STAGE_B; // 49152 B

constexpr uint32_t OFF_FULL    = 0;    // 3 x 8B
constexpr uint32_t OFF_EMPTY   = 24;   // 3 x 8B
constexpr uint32_t OFF_TILEBAR = 48;   // 8B, count=1
constexpr uint32_t OFF_RING    = 64;   // 8 x int
constexpr uint32_t OFF_DATA    = 1024;
constexpr uint32_t SMEM_SIZE = OFF_DATA + STAGES * STAGE_BYTES;  // 148480

// fused prepass grid split
constexpr int DQ_BLOCKS_X = kN / 128;                // 112
constexpr int DQ_BLOCKS   = DQ_BLOCKS_X * (kK / 32); // 14336
constexpr int CV_BLOCKS   = (int)(((size_t)kM * kK) / (8 * 256)); // 8192

// ---------------- device scratch ----------------
__device__ __align__(1024) __half g_W[(size_t)kN * kK];  // dequantized, [N,K] K-major
__device__ __align__(1024) __half g_X[(size_t)kM * kK];  // fp16 activations [M,K]
__device__ int g_ctr;                                    // persistent tile counter

// ---------------- PTX helpers ----------------
__device__ __forceinline__ uint32_t smem_u32(const void* p) {
    uint32_t a;
    asm("{ .reg .u64 t; cvta.to.shared.u64 t, %1; cvt.u32.u64 %0, t; }" : "=r"(a) : "l"(p));
    return a;
}

#define MBARRIER_INIT(addr, cnt) \
    asm volatile("mbarrier.init.shared.b64 [%0], %1;" :: "r"(addr), "r"(cnt) : "memory")

#define MBARRIER_ARRIVE(addr) \
    asm volatile("mbarrier.arrive.shared.b64 _, [%0];" :: "r"(addr) : "memory")

#define MBARRIER_EXPECT_TX(addr, bytes) \
    asm volatile("mbarrier.arrive.expect_tx.shared.b64 _, [%0], %1;" :: "r"(addr), "r"(bytes) : "memory")

#define MBARRIER_WAIT_PARITY(addr, parity) do {                                      \
    uint32_t _mbar = (addr); uint32_t _par = (parity); uint32_t _done;               \
    asm volatile("{\n\t.reg .pred p;\n\t"                                            \
        "mbarrier.try_wait.parity.acquire.cta.shared::cta.b64 p, [%1], %2;\n\t"      \
        "selp.b32 %0, 1, 0, p;\n\t}"                                                 \
        : "=r"(_done) : "r"(_mbar), "r"(_par) : "memory");                           \
    if (!_done) {                                                                    \
        asm volatile("{\n\t.reg .pred P1;\n\t"                                       \
            "WAIT_LOOP_%=:\n\t"                                                      \
            "mbarrier.try_wait.parity.acquire.cta.shared::cta.b64 P1, [%0], %1, 0x989680;\n\t" \
            "@P1 bra.uni WAIT_DONE_%=;\n\t"                                          \
            "bra.uni WAIT_LOOP_%=;\n\t"                                              \
            "WAIT_DONE_%=:\n\t}"                                                     \
            :: "r"(_mbar), "r"(_par) : "memory");                                    \
    }                                                                                \
} while (0)

#define TMA_LOAD_2D(smem_addr, map_ptr, cx, cy, mbar) \
    asm volatile("cp.async.bulk.tensor.2d.shared::cta.global.tile.mbarrier::complete_tx::bytes " \
                 "[%0], [%1, {%2, %3}], [%4];" \
                 :: "r"((uint32_t)(smem_addr)), "l"(map_ptr), "r"((int)(cx)), "r"((int)(cy)), \
                    "r"((uint32_t)(mbar)) : "memory")

__device__ __forceinline__ void ldsm_x4(uint32_t (&r)[4], uint32_t addr) {
    asm volatile("ldmatrix.sync.aligned.m8n8.x4.shared.b16 {%0,%1,%2,%3}, [%4];"
                 : "=r"(r[0]), "=r"(r[1]), "=r"(r[2]), "=r"(r[3]) : "r"(addr));
}

__device__ __forceinline__ void mma_16816(float (&d)[4], const uint32_t (&a)[4],
                                          uint32_t b0, uint32_t b1) {
    asm volatile(
        "mma.sync.aligned.m16n8k16.row.col.f32.f16.f16.f32 "
        "{%0,%1,%2,%3}, {%4,%5,%6,%7}, {%8,%9}, {%0,%1,%2,%3};"
        : "+f"(d[0]), "+f"(d[1]), "+f"(d[2]), "+f"(d[3])
        : "r"(a[0]), "r"(a[1]), "r"(a[2]), "r"(a[3]), "r"(b0), "r"(b1));
}

// ---------------- fused pre-pass (exact R11 + counter reset) ----------------
__global__ void k_prepass(const float* __restrict__ x,
                          const int* __restrict__ q,
                          const float* __restrict__ s) {
    __shared__ __half t[128][34];
    int b = blockIdx.x;
    int tid = threadIdx.x;

    if (b == 0 && tid == 0) g_ctr = GRID;   // reset tile counter (graph replay safe)

    if (b < DQ_BLOCKS) {
        int n0 = (b % DQ_BLOCKS_X) * 128;
        int k0 = (b / DQ_BLOCKS_X) * 32;
        int nq = (tid & 31) * 4;
        int kb = tid >> 5;
        int g = k0 >> 6;

        float4 sc4 = *reinterpret_cast<const float4*>(s + (size_t)g * kN + n0 + nq);

#pragma unroll
        for (int p = 0; p < 4; ++p) {
            int k = p * 8 + kb;
            int4 qv = *reinterpret_cast<const int4*>(q + (size_t)(k0 + k) * kN + n0 + nq);
            t[nq + 0][k] = __float2half((float)(qv.x - 8) * sc4.x);
            t[nq + 1][k] = __float2half((float)(qv.y - 8) * sc4.y);
            t[nq + 2][k] = __float2half((float)(qv.z - 8) * sc4.z);
            t[nq + 3][k] = __float2half((float)(qv.w - 8) * sc4.w);
        }
        __syncthreads();

        int n = tid >> 1, seg = tid & 1;
        const uint32_t* src = reinterpret_cast<const uint32_t*>(&t[n][seg * 16]);
        uint32_t r[8];
#pragma unroll
        for (int i = 0; i < 8; ++i) r[i] = src[i];
        float4* dst = reinterpret_cast<float4*>(g_W + (size_t)(n0 + n) * kK + k0 + seg * 16);
        dst[0] = make_float4(__uint_as_float(r[0]), __uint_as_float(r[1]),
                             __uint_as_float(r[2]), __uint_as_float(r[3]));
        dst[1] = make_float4(__uint_as_float(r[4]), __uint_as_float(r[5]),
                             __uint_as_float(r[6]), __uint_as_float(r[7]));
    } else {
        size_t i = (size_t)(b - DQ_BLOCKS) * blockDim.x + tid;
        float4 v0 = reinterpret_cast<const float4*>(x)[2 * i];
        float4 v1 = reinterpret_cast<const float4*>(x)[2 * i + 1];
        __half2 h0 = __floats2half2_rn(v0.x, v0.y);
        __half2 h1 = __floats2half2_rn(v0.z, v0.w);
        __half2 h2 = __floats2half2_rn(v1.x, v1.y);
        __half2 h3 = __floats2half2_rn(v1.z, v1.w);
        float4 o;
        o.x = __uint_as_float(*reinterpret_cast<uint32_t*>(&h0));
        o.y = __uint_as_float(*reinterpret_cast<uint32_t*>(&h1));
        o.z = __uint_as_float(*reinterpret_cast<uint32_t*>(&h2));
        o.w = __uint_as_float(*reinterpret_cast<uint32_t*>(&h3));
        reinterpret_cast<float4*>(g_X)[i] = o;
    }
}

// ---- GEMM: dynamic-persistent; continuous 3-stage pipeline across tiles ----
__global__ void __launch_bounds__(288, 1) k_gemm(
    const __grid_constant__ CUtensorMap tma_a,
    const __grid_constant__ CUtensorMap tma_b,
    float* __restrict__ out)
{
    extern __shared__ char smem[];
    uint32_t sb = smem_u32(smem);
    int tid = threadIdx.x, wid = tid >> 5, lane = tid & 31;
    int* ring = reinterpret_cast<int*>(smem + OFF_RING);

    if (tid == 0) {
#pragma unroll
        for (int s = 0; s < STAGES; s++) {
            MBARRIER_INIT(sb + OFF_FULL + 8 * s, 1);
            MBARRIER_INIT(sb + OFF_EMPTY + 8 * s, 8);
        }
        MBARRIER_INIT(sb + OFF_TILEBAR, 1);
    }
    __syncthreads();

    if (wid == 8) {
        // -------- producer warp: streams tiles claimed via atomicAdd --------
        if (lane == 0) {
            int c = 0;
            int t = blockIdx.x;                   // first tile static
            ring[0] = t;
            MBARRIER_ARRIVE(sb + OFF_TILEBAR);    // release: publishes ring[0]
            int m0 = (t & (NTM - 1)) * TM;
            int n0 = (t >> 5) * TN;
            // one-time prologue: first 3 k-slices
#pragma unroll
            for (int s = 0; s < STAGES; s++) {
                MBARRIER_EXPECT_TX(sb + OFF_FULL + 8 * s, STAGE_BYTES);
                uint32_t base = sb + OFF_DATA + s * STAGE_BYTES;
                TMA_LOAD_2D(base,           &tma_a, s * TK, m0, sb + OFF_FULL + 8 * s);
                TMA_LOAD_2D(base + STAGE_A, &tma_b, s * TK, n0, sb + OFF_FULL + 8 * s);
            }
            int pe0 = 0, pe1 = 0, pe2 = 0;
            int s = 0, km = STAGES;
            for (;;) {
                if (km == KITERS) {
                    c++;
                    t = atomicAdd(&g_ctr, 1);     // dynamic steal
                    ring[c & 7] = t;
                    MBARRIER_ARRIVE(sb + OFF_TILEBAR);
                    if (t >= NTILES) break;
                    m0 = (t & (NTM - 1)) * TM;
                    n0 = (t >> 5) * TN;
                    km = 0;
                }
                int& pe = (s == 0) ? pe0 : (s == 1) ? pe1 : pe2;
                MBARRIER_WAIT_PARITY(sb + OFF_EMPTY + 8 * s, pe); pe ^= 1;
                MBARRIER_EXPECT_TX(sb + OFF_FULL + 8 * s, STAGE_BYTES);
                uint32_t base = sb + OFF_DATA + s * STAGE_BYTES;
                TMA_LOAD_2D(base,           &tma_a, km * TK, m0, sb + OFF_FULL + 8 * s);
                TMA_LOAD_2D(base + STAGE_A, &tma_b, km * TK, n0, sb + OFF_FULL + 8 * s);
                km++;
                if (++s == 3) s = 0;
            }
        }
        return;
    }

    // -------- compute warps (8): each owns a 64x64 sub-tile --------
    const int warp_m = wid & 1;
    const int warp_n = wid >> 1;
    const uint32_t swz = (uint32_t)(lane & 7) << 4;
    const uint32_t aOff0 = (uint32_t)(warp_m * 64 + (lane & 15)) * 128 + (uint32_t)(lane >> 4) * 16;
    const int grp = lane >> 3;
    const uint32_t bOff0 = (uint32_t)(warp_n * 64 + (grp >> 1) * 8 + (lane & 7)) * 128
                         + (uint32_t)(grp & 1) * 16;
    const int m_off = warp_m * 64 + (lane >> 2);
    const int n_off = warp_n * 64 + (lane & 3) * 2;

    int c = 0, tipar = 0;
    int s = 0;
    int pf0 = 0, pf1 = 0, pf2 = 0;

#pragma unroll 1
    for (;;) {
        MBARRIER_WAIT_PARITY(sb + OFF_TILEBAR, tipar); tipar ^= 1;   // acquire ring[c]
        int t = ring[c & 7];
        if (t >= NTILES) break;

        float acc[4][8][4];
#pragma unroll
        for (int i = 0; i < 4; i++)
#pragma unroll
            for (int j = 0; j < 8; j++)
#pragma unroll
                for (int cc = 0; cc < 4; cc++) acc[i][j][cc] = 0.0f;

        for (int it = 0; it < KITERS; ++it) {
            int& pf = (s == 0) ? pf0 : (s == 1) ? pf1 : pf2;
            MBARRIER_WAIT_PARITY(sb + OFF_FULL + 8 * s, pf); pf ^= 1;
            uint32_t sA = sb + OFF_DATA + s * STAGE_BYTES;
            uint32_t sB = sA + STAGE_A;

#pragma unroll
            for (int ks = 0; ks < 4; ++ks) {
                uint32_t a_frag[4][4];
                uint32_t b_frag[4][4];
#pragma unroll
                for (int mt = 0; mt < 4; ++mt)
                    ldsm_x4(a_frag[mt], (sA + aOff0 + mt * 2048 + ks * 32) ^ swz);
#pragma unroll
                for (int nt2 = 0; nt2 < 4; ++nt2)
                    ldsm_x4(b_frag[nt2], (sB + bOff0 + nt2 * 2048 + ks * 32) ^ swz);
#pragma unroll
                for (int mt = 0; mt < 4; ++mt) {
#pragma unroll
                    for (int nt2 = 0; nt2 < 4; ++nt2) {
                        mma_16816(acc[mt][2 * nt2 + 0], a_frag[mt], b_frag[nt2][0], b_frag[nt2][1]);
                        mma_16816(acc[mt][2 * nt2 + 1], a_frag[mt], b_frag[nt2][2], b_frag[nt2][3]);
                    }
                }
            }
            if (lane == 0) MBARRIER_ARRIVE(sb + OFF_EMPTY + 8 * s);
            if (++s == 3) s = 0;
        }

        // -------- per-tile epilogue (outside hot loop) --------
        {
            int tile_m = t & (NTM - 1);
            int tile_n = t >> 5;
            float* dst = out + ((size_t)tile_m * TM) * kN + (size_t)tile_n * TN;
#pragma unroll
            for (int mt = 0; mt < 4; ++mt) {
                float* row1 = dst + (size_t)(m_off + mt * 16) * kN + n_off;
                float* row2 = row1 + 8 * (size_t)kN;
#pragma unroll
                for (int nt = 0; nt < 8; ++nt) {
                    *reinterpret_cast<float2*>(row1 + nt * 8) = make_float2(acc[mt][nt][0], acc[mt][nt][1]);
                    *reinterpret_cast<float2*>(row2 + nt * 8) = make_float2(acc[mt][nt][2], acc[mt][nt][3]);
                }
            }
        }
        c++;
    }
}

// ---------------- host: tensor maps + launches ----------------
typedef CUresult (CUDAAPI *tmap_encode_fn)(
    CUtensorMap*, CUtensorMapDataType, cuuint32_t, void*,
    const cuuint64_t*, const cuuint64_t*, const cuuint32_t*, const cuuint32_t*,
    CUtensorMapInterleave, CUtensorMapSwizzle, CUtensorMapL2promotion, CUtensorMapFloatOOBfill);

static tmap_encode_fn get_encoder() {
    void* fn = nullptr;
    cudaDriverEntryPointQueryResult st;
    cudaGetDriverEntryPointByVersion("cuTensorMapEncodeTiled", &fn, 12000,
                                     cudaEnableDefault, &st);
    return (tmap_encode_fn)fn;
}

extern "C" void kernel_launch(void* const* d_in, const int* in_sizes, int n_in,
                              void* d_out, int out_size) {
    const float* x = (const float*)d_in[0];
    const int*   q = (const int*)d_in[1];
    const float* s = (const float*)d_in[2];
    float* out = (float*)d_out;

    k_prepass<<<DQ_BLOCKS + CV_BLOCKS, 256>>>(x, q, s);

    void* pX = nullptr; void* pW = nullptr;
    cudaGetSymbolAddress(&pX, g_X);
    cudaGetSymbolAddress(&pW, g_W);
    tmap_encode_fn enc = get_encoder();

    CUtensorMap ta, tb;
    {
        cuuint64_t dims[2]    = {(cuuint64_t)kK, (cuuint64_t)kM};
        cuuint64_t strides[1] = {(cuuint64_t)kK * 2};
        cuuint32_t box[2]     = {(cuuint32_t)TK, (cuuint32_t)TM};
        cuuint32_t estr[2]    = {1, 1};
        enc(&ta, CU_TENSOR_MAP_DATA_TYPE_FLOAT16, 2, pX, dims, strides, box, estr,
            CU_TENSOR_MAP_INTERLEAVE_NONE, CU_TENSOR_MAP_SWIZZLE_128B,
            CU_TENSOR_MAP_L2_PROMOTION_L2_128B, CU_TENSOR_MAP_FLOAT_OOB_FILL_NONE);
    }
    {
        cuuint64_t dims[2]    = {(cuuint64_t)kK, (cuuint64_t)kN};
        cuuint64_t strides[1] = {(cuuint64_t)kK * 2};
        cuuint32_t box[2]     = {(cuuint32_t)TK, (cuuint32_t)TN};
        cuuint32_t estr[2]    = {1, 1};
        enc(&tb, CU_TENSOR_MAP_DATA_TYPE_FLOAT16, 2, pW, dims, strides, box, estr,
            CU_TENSOR_MAP_INTERLEAVE_NONE, CU_TENSOR_MAP_SWIZZLE_128B,
            CU_TENSOR_MAP_L2_PROMOTION_L2_128B, CU_TENSOR_MAP_FLOAT_OOB_FILL_NONE);
    }

    cudaFuncSetAttribute(k_gemm, cudaFuncAttributeMaxDynamicSharedMemorySize, SMEM_SIZE);
    k_gemm<<<GRID, 288, SMEM_SIZE>>>(ta, tb, out);
}

// round 15
// speedup vs baseline: 1.1754x; 1.1754x over previous
#include <cuda_runtime.h>
#include <cuda_fp16.h>
#include <cuda.h>
#include <cudaTypedefs.h>
#include <cstdint>

// ---------------- problem constants ----------------
constexpr int kM = 4096, kK = 4096, kN = 14336;
constexpr int TM = 128, TN = 256, TK = 64;
constexpr int KITERS = kK / TK;            // 64
constexpr int NTM = kM / TM;               // 32
constexpr int NTN = kN / TN;               // 56
constexpr int NTILES = NTM * NTN;          // 1792
constexpr int STAGES = 3;
constexpr uint32_t STAGE_A = TM * TK * 2;          // 16384 B
constexpr uint32_t STAGE_B = TN * TK * 2;          // 32768 B
constexpr uint32_t STAGE_BYTES = STAGE_A + STAGE_B; // 49152 B

constexpr uint32_t OFF_FULL  = 0;
constexpr uint32_t OFF_EMPTY = 24;
constexpr uint32_t OFF_DATA  = 1024;
constexpr uint32_t SMEM_SIZE = OFF_DATA + STAGES * STAGE_BYTES;  // 148480

// fused prepass grid split
constexpr int DQ_BLOCKS_X = kN / 128;                // 112
constexpr int DQ_BLOCKS   = DQ_BLOCKS_X * (kK / 32); // 14336
constexpr int CV_BLOCKS   = (int)(((size_t)kM * kK) / (8 * 256)); // 8192

// ---------------- device scratch ----------------
__device__ __align__(1024) __half g_W[(size_t)kN * kK];  // dequantized, [N,K] K-major
__device__ __align__(1024) __half g_X[(size_t)kM * kK];  // fp16 activations [M,K]

// ---------------- PTX helpers ----------------
__device__ __forceinline__ uint32_t smem_u32(const void* p) {
    uint32_t a;
    asm("{ .reg .u64 t; cvta.to.shared.u64 t, %1; cvt.u32.u64 %0, t; }" : "=r"(a) : "l"(p));
    return a;
}

#define MBARRIER_INIT(addr, cnt) \
    asm volatile("mbarrier.init.shared.b64 [%0], %1;" :: "r"(addr), "r"(cnt) : "memory")

#define MBARRIER_ARRIVE(addr) \
    asm volatile("mbarrier.arrive.shared.b64 _, [%0];" :: "r"(addr) : "memory")

#define MBARRIER_EXPECT_TX(addr, bytes) \
    asm volatile("mbarrier.arrive.expect_tx.shared.b64 _, [%0], %1;" :: "r"(addr), "r"(bytes) : "memory")

#define MBARRIER_WAIT_PARITY(addr, parity) do {                                      \
    uint32_t _mbar = (addr); uint32_t _par = (parity); uint32_t _done;               \
    asm volatile("{\n\t.reg .pred p;\n\t"                                            \
        "mbarrier.try_wait.parity.acquire.cta.shared::cta.b64 p, [%1], %2;\n\t"      \
        "selp.b32 %0, 1, 0, p;\n\t}"                                                 \
        : "=r"(_done) : "r"(_mbar), "r"(_par) : "memory");                           \
    if (!_done) {                                                                    \
        asm volatile("{\n\t.reg .pred P1;\n\t"                                       \
            "WAIT_LOOP_%=:\n\t"                                                      \
            "mbarrier.try_wait.parity.acquire.cta.shared::cta.b64 P1, [%0], %1, 0x989680;\n\t" \
            "@P1 bra.uni WAIT_DONE_%=;\n\t"                                          \
            "bra.uni WAIT_LOOP_%=;\n\t"                                              \
            "WAIT_DONE_%=:\n\t}"                                                     \
            :: "r"(_mbar), "r"(_par) : "memory");                                    \
    }                                                                                \
} while (0)

#define TMA_LOAD_2D(smem_addr, map_ptr, cx, cy, mbar) \
    asm volatile("cp.async.bulk.tensor.2d.shared::cta.global.tile.mbarrier::complete_tx::bytes " \
                 "[%0], [%1, {%2, %3}], [%4];" \
                 :: "r"((uint32_t)(smem_addr)), "l"(map_ptr), "r"((int)(cx)), "r"((int)(cy)), \
                    "r"((uint32_t)(mbar)) : "memory")

__device__ __forceinline__ void ldsm_x4(uint32_t (&r)[4], uint32_t addr) {
    asm volatile("ldmatrix.sync.aligned.m8n8.x4.shared.b16 {%0,%1,%2,%3}, [%4];"
                 : "=r"(r[0]), "=r"(r[1]), "=r"(r[2]), "=r"(r[3]) : "r"(addr));
}

__device__ __forceinline__ void mma_16816(float (&d)[4], const uint32_t (&a)[4],
                                          uint32_t b0, uint32_t b1) {
    asm volatile(
        "mma.sync.aligned.m16n8k16.row.col.f32.f16.f16.f32 "
        "{%0,%1,%2,%3}, {%4,%5,%6,%7}, {%8,%9}, {%0,%1,%2,%3};"
        : "+f"(d[0]), "+f"(d[1]), "+f"(d[2]), "+f"(d[3])
        : "r"(a[0]), "r"(a[1]), "r"(a[2]), "r"(a[3]), "r"(b0), "r"(b1));
}

// ---------------- fused pre-pass (exact R11) ----------------
__global__ void k_prepass(const float* __restrict__ x,
                          const int* __restrict__ q,
                          const float* __restrict__ s) {
    __shared__ __half t[128][34];
    int b = blockIdx.x;
    int tid = threadIdx.x;

    if (b < DQ_BLOCKS) {
        int n0 = (b % DQ_BLOCKS_X) * 128;
        int k0 = (b / DQ_BLOCKS_X) * 32;
        int nq = (tid & 31) * 4;
        int kb = tid >> 5;
        int g = k0 >> 6;

        float4 sc4 = *reinterpret_cast<const float4*>(s + (size_t)g * kN + n0 + nq);

#pragma unroll
        for (int p = 0; p < 4; ++p) {
            int k = p * 8 + kb;
            int4 qv = *reinterpret_cast<const int4*>(q + (size_t)(k0 + k) * kN + n0 + nq);
            t[nq + 0][k] = __float2half((float)(qv.x - 8) * sc4.x);
            t[nq + 1][k] = __float2half((float)(qv.y - 8) * sc4.y);
            t[nq + 2][k] = __float2half((float)(qv.z - 8) * sc4.z);
            t[nq + 3][k] = __float2half((float)(qv.w - 8) * sc4.w);
        }
        __syncthreads();

        int n = tid >> 1, seg = tid & 1;
        const uint32_t* src = reinterpret_cast<const uint32_t*>(&t[n][seg * 16]);
        uint32_t r[8];
#pragma unroll
        for (int i = 0; i < 8; ++i) r[i] = src[i];
        float4* dst = reinterpret_cast<float4*>(g_W + (size_t)(n0 + n) * kK + k0 + seg * 16);
        dst[0] = make_float4(__uint_as_float(r[0]), __uint_as_float(r[1]),
                             __uint_as_float(r[2]), __uint_as_float(r[3]));
        dst[1] = make_float4(__uint_as_float(r[4]), __uint_as_float(r[5]),
                             __uint_as_float(r[6]), __uint_as_float(r[7]));
    } else {
        size_t i = (size_t)(b - DQ_BLOCKS) * blockDim.x + tid;
        float4 v0 = reinterpret_cast<const float4*>(x)[2 * i];
        float4 v1 = reinterpret_cast<const float4*>(x)[2 * i + 1];
        __half2 h0 = __floats2half2_rn(v0.x, v0.y);
        __half2 h1 = __floats2half2_rn(v0.z, v0.w);
        __half2 h2 = __floats2half2_rn(v1.x, v1.y);
        __half2 h3 = __floats2half2_rn(v1.z, v1.w);
        float4 o;
        o.x = __uint_as_float(*reinterpret_cast<uint32_t*>(&h0));
        o.y = __uint_as_float(*reinterpret_cast<uint32_t*>(&h1));
        o.z = __uint_as_float(*reinterpret_cast<uint32_t*>(&h2));
        o.w = __uint_as_float(*reinterpret_cast<uint32_t*>(&h3));
        reinterpret_cast<float4*>(g_X)[i] = o;
    }
}

// ---- GEMM: 128x256 tile, HMMA mma.sync, 3-stage TMA pipeline (EXACT R11) ---
__global__ void __launch_bounds__(288, 1) k_gemm(
    const __grid_constant__ CUtensorMap tma_a,
    const __grid_constant__ CUtensorMap tma_b,
    float* __restrict__ out)
{
    extern __shared__ char smem[];
    uint32_t sb = smem_u32(smem);
    int tid = threadIdx.x, wid = tid >> 5, lane = tid & 31;
    int tile_m = blockIdx.x % NTM;   // m-fastest: consecutive CTAs share B tiles in L2
    int tile_n = blockIdx.x / NTM;

    if (tid == 0) {
#pragma unroll
        for (int s = 0; s < STAGES; s++) {
            MBARRIER_INIT(sb + OFF_FULL + 8 * s, 1);
            MBARRIER_INIT(sb + OFF_EMPTY + 8 * s, 8);
        }
    }
    __syncthreads();

    if (wid == 8) {
        // ---------------- producer warp ----------------
        if (lane == 0) {
            const int m0 = tile_m * TM;
            const int n0 = tile_n * TN;
#pragma unroll
            for (int s = 0; s < STAGES; s++) {
                MBARRIER_EXPECT_TX(sb + OFF_FULL + 8 * s, STAGE_BYTES);
                uint32_t base = sb + OFF_DATA + s * STAGE_BYTES;
                TMA_LOAD_2D(base,           &tma_a, s * TK, m0, sb + OFF_FULL + 8 * s);
                TMA_LOAD_2D(base + STAGE_A, &tma_b, s * TK, n0, sb + OFF_FULL + 8 * s);
            }
            int pe0 = 0, pe1 = 0, pe2 = 0;
            for (int it = STAGES; it < KITERS; ++it) {
                int s = it % 3;
                int& pe = (s == 0) ? pe0 : (s == 1) ? pe1 : pe2;
                MBARRIER_WAIT_PARITY(sb + OFF_EMPTY + 8 * s, pe); pe ^= 1;
                MBARRIER_EXPECT_TX(sb + OFF_FULL + 8 * s, STAGE_BYTES);
                uint32_t base = sb + OFF_DATA + s * STAGE_BYTES;
                TMA_LOAD_2D(base,           &tma_a, it * TK, m0, sb + OFF_FULL + 8 * s);
                TMA_LOAD_2D(base + STAGE_A, &tma_b, it * TK, n0, sb + OFF_FULL + 8 * s);
            }
        }
        return;
    }

    // ---------------- compute warps (8): each owns a 64x64 sub-tile ----------
    const int warp_m = wid & 1;
    const int warp_n = wid >> 1;
    const uint32_t swz = (uint32_t)(lane & 7) << 4;

    const uint32_t aOff0 = (uint32_t)(warp_m * 64 + (lane & 15)) * 128 + (uint32_t)(lane >> 4) * 16;
    const int grp = lane >> 3;
    const uint32_t bOff0 = (uint32_t)(warp_n * 64 + (grp >> 1) * 8 + (lane & 7)) * 128
                         + (uint32_t)(grp & 1) * 16;

    float acc[4][8][4];
#pragma unroll
    for (int i = 0; i < 4; i++)
#pragma unroll
        for (int j = 0; j < 8; j++)
#pragma unroll
            for (int c = 0; c < 4; c++) acc[i][j][c] = 0.0f;

    int pf0 = 0, pf1 = 0, pf2 = 0;
    for (int it = 0; it < KITERS; ++it) {
        int s = it % 3;
        int& pf = (s == 0) ? pf0 : (s == 1) ? pf1 : pf2;
        MBARRIER_WAIT_PARITY(sb + OFF_FULL + 8 * s, pf); pf ^= 1;
        uint32_t sA = sb + OFF_DATA + s * STAGE_BYTES;
        uint32_t sB = sA + STAGE_A;

#pragma unroll
        for (int ks = 0; ks < 4; ++ks) {
            uint32_t a_frag[4][4];
            uint32_t b_frag[4][4];
#pragma unroll
            for (int mt = 0; mt < 4; ++mt)
                ldsm_x4(a_frag[mt], (sA + aOff0 + mt * 2048 + ks * 32) ^ swz);
#pragma unroll
            for (int nt2 = 0; nt2 < 4; ++nt2)
                ldsm_x4(b_frag[nt2], (sB + bOff0 + nt2 * 2048 + ks * 32) ^ swz);
#pragma unroll
            for (int mt = 0; mt < 4; ++mt) {
#pragma unroll
                for (int nt2 = 0; nt2 < 4; ++nt2) {
                    mma_16816(acc[mt][2 * nt2 + 0], a_frag[mt], b_frag[nt2][0], b_frag[nt2][1]);
                    mma_16816(acc[mt][2 * nt2 + 1], a_frag[mt], b_frag[nt2][2], b_frag[nt2][3]);
                }
            }
        }
        if (lane == 0) MBARRIER_ARRIVE(sb + OFF_EMPTY + 8 * s);
    }

    // ---------------- epilogue: direct fp32 stores ----------------
    float* dst = out + ((size_t)tile_m * TM) * kN + (size_t)tile_n * TN;
    const int m_off = warp_m * 64 + (lane >> 2);
    const int n_off = warp_n * 64 + (lane & 3) * 2;
#pragma unroll
    for (int mt = 0; mt < 4; ++mt) {
        float* row1 = dst + (size_t)(m_off + mt * 16) * kN + n_off;
        float* row2 = row1 + 8 * (size_t)kN;
#pragma unroll
        for (int nt = 0; nt < 8; ++nt) {
            *reinterpret_cast<float2*>(row1 + nt * 8) = make_float2(acc[mt][nt][0], acc[mt][nt][1]);
            *reinterpret_cast<float2*>(row2 + nt * 8) = make_float2(acc[mt][nt][2], acc[mt][nt][3]);
        }
    }
}

// ---------------- host: tensor maps + launches ----------------
typedef CUresult (CUDAAPI *tmap_encode_fn)(
    CUtensorMap*, CUtensorMapDataType, cuuint32_t, void*,
    const cuuint64_t*, const cuuint64_t*, const cuuint32_t*, const cuuint32_t*,
    CUtensorMapInterleave, CUtensorMapSwizzle, CUtensorMapL2promotion, CUtensorMapFloatOOBfill);

static tmap_encode_fn get_encoder() {
    void* fn = nullptr;
    cudaDriverEntryPointQueryResult st;
    cudaGetDriverEntryPointByVersion("cuTensorMapEncodeTiled", &fn, 12000,
                                     cudaEnableDefault, &st);
    return (tmap_encode_fn)fn;
}

extern "C" void kernel_launch(void* const* d_in, const int* in_sizes, int n_in,
                              void* d_out, int out_size) {
    const float* x = (const float*)d_in[0];
    const int*   q = (const int*)d_in[1];
    const float* s = (const float*)d_in[2];
    float* out = (float*)d_out;

    k_prepass<<<DQ_BLOCKS + CV_BLOCKS, 256>>>(x, q, s);

    void* pX = nullptr; void* pW = nullptr;
    cudaGetSymbolAddress(&pX, g_X);
    cudaGetSymbolAddress(&pW, g_W);
    tmap_encode_fn enc = get_encoder();

    CUtensorMap ta, tb;
    {
        cuuint64_t dims[2]    = {(cuuint64_t)kK, (cuuint64_t)kM};
        cuuint64_t strides[1] = {(cuuint64_t)kK * 2};
        cuuint32_t box[2]     = {(cuuint32_t)TK, (cuuint32_t)TM};
        cuuint32_t estr[2]    = {1, 1};
        enc(&ta, CU_TENSOR_MAP_DATA_TYPE_FLOAT16, 2, pX, dims, strides, box, estr,
            CU_TENSOR_MAP_INTERLEAVE_NONE, CU_TENSOR_MAP_SWIZZLE_128B,
            CU_TENSOR_MAP_L2_PROMOTION_L2_256B, CU_TENSOR_MAP_FLOAT_OOB_FILL_NONE);
    }
    {
        cuuint64_t dims[2]    = {(cuuint64_t)kK, (cuuint64_t)kN};
        cuuint64_t strides[1] = {(cuuint64_t)kK * 2};
        cuuint32_t box[2]     = {(cuuint32_t)TK, (cuuint32_t)TN};
        cuuint32_t estr[2]    = {1, 1};
        enc(&tb, CU_TENSOR_MAP_DATA_TYPE_FLOAT16, 2, pW, dims, strides, box, estr,
            CU_TENSOR_MAP_INTERLEAVE_NONE, CU_TENSOR_MAP_SWIZZLE_128B,
            CU_TENSOR_MAP_L2_PROMOTION_L2_256B, CU_TENSOR_MAP_FLOAT_OOB_FILL_NONE);
    }

    cudaFuncSetAttribute(k_gemm, cudaFuncAttributeMaxDynamicSharedMemorySize, SMEM_SIZE);
    k_gemm<<<NTILES, 288, SMEM_SIZE>>>(ta, tb, out);
}

// round 16
// speedup vs baseline: 1.1975x; 1.0188x over previous
#include <cuda_runtime.h>
#include <cuda_fp16.h>
#include <cuda.h>
#include <cudaTypedefs.h>
#include <cstdint>

// ---------------- problem constants ----------------
constexpr int kM = 4096, kK = 4096, kN = 14336;
constexpr int TM = 128, TN = 256;
constexpr int TKB = 64;                    // TMA box width (SW128 limit: 64 fp16)
constexpr int TK = 128;                    // k-chunk per stage (2 sub-tiles)
constexpr int KITERS = kK / TK;            // 32
constexpr int NTM = kM / TM;               // 32
constexpr int NTN = kN / TN;               // 56
constexpr int NTILES = NTM * NTN;          // 1792
constexpr int STAGES = 2;
constexpr uint32_t SUB_A   = TM * TKB * 2;          // 16384 B
constexpr uint32_t SUB_B   = TN * TKB * 2;          // 32768 B
constexpr uint32_t STAGE_A = 2 * SUB_A;             // 32768 B
constexpr uint32_t STAGE_B = 2 * SUB_B;             // 65536 B
constexpr uint32_t STAGE_BYTES = STAGE_A + STAGE_B; // 98304 B

constexpr uint32_t OFF_FULL  = 0;
constexpr uint32_t OFF_EMPTY = 16;
constexpr uint32_t OFF_DATA  = 1024;
constexpr uint32_t SMEM_SIZE = OFF_DATA + STAGES * STAGE_BYTES;  // 197632

// fused prepass grid split
constexpr int DQ_BLOCKS_X = kN / 128;                // 112
constexpr int DQ_BLOCKS   = DQ_BLOCKS_X * (kK / 32); // 14336
constexpr int CV_BLOCKS   = (int)(((size_t)kM * kK) / (8 * 256)); // 8192

// ---------------- device scratch ----------------
__device__ __align__(1024) __half g_W[(size_t)kN * kK];  // dequantized, [N,K] K-major
__device__ __align__(1024) __half g_X[(size_t)kM * kK];  // fp16 activations [M,K]

// ---------------- PTX helpers ----------------
__device__ __forceinline__ uint32_t smem_u32(const void* p) {
    uint32_t a;
    asm("{ .reg .u64 t; cvta.to.shared.u64 t, %1; cvt.u32.u64 %0, t; }" : "=r"(a) : "l"(p));
    return a;
}

#define MBARRIER_INIT(addr, cnt) \
    asm volatile("mbarrier.init.shared.b64 [%0], %1;" :: "r"(addr), "r"(cnt) : "memory")

#define MBARRIER_ARRIVE(addr) \
    asm volatile("mbarrier.arrive.shared.b64 _, [%0];" :: "r"(addr) : "memory")

#define MBARRIER_EXPECT_TX(addr, bytes) \
    asm volatile("mbarrier.arrive.expect_tx.shared.b64 _, [%0], %1;" :: "r"(addr), "r"(bytes) : "memory")

#define MBARRIER_WAIT_PARITY(addr, parity) do {                                      \
    uint32_t _mbar = (addr); uint32_t _par = (parity); uint32_t _done;               \
    asm volatile("{\n\t.reg .pred p;\n\t"                                            \
        "mbarrier.try_wait.parity.acquire.cta.shared::cta.b64 p, [%1], %2;\n\t"      \
        "selp.b32 %0, 1, 0, p;\n\t}"                                                 \
        : "=r"(_done) : "r"(_mbar), "r"(_par) : "memory");                           \
    if (!_done) {                                                                    \
        asm volatile("{\n\t.reg .pred P1;\n\t"                                       \
            "WAIT_LOOP_%=:\n\t"                                                      \
            "mbarrier.try_wait.parity.acquire.cta.shared::cta.b64 P1, [%0], %1, 0x989680;\n\t" \
            "@P1 bra.uni WAIT_DONE_%=;\n\t"                                          \
            "bra.uni WAIT_LOOP_%=;\n\t"                                              \
            "WAIT_DONE_%=:\n\t}"                                                     \
            :: "r"(_mbar), "r"(_par) : "memory");                                    \
    }                                                                                \
} while (0)

#define TMA_LOAD_2D(smem_addr, map_ptr, cx, cy, mbar) \
    asm volatile("cp.async.bulk.tensor.2d.shared::cta.global.tile.mbarrier::complete_tx::bytes " \
                 "[%0], [%1, {%2, %3}], [%4];" \
                 :: "r"((uint32_t)(smem_addr)), "l"(map_ptr), "r"((int)(cx)), "r"((int)(cy)), \
                    "r"((uint32_t)(mbar)) : "memory")

__device__ __forceinline__ void ldsm_x4(uint32_t (&r)[4], uint32_t addr) {
    asm volatile("ldmatrix.sync.aligned.m8n8.x4.shared.b16 {%0,%1,%2,%3}, [%4];"
                 : "=r"(r[0]), "=r"(r[1]), "=r"(r[2]), "=r"(r[3]) : "r"(addr));
}

__device__ __forceinline__ void mma_16816(float (&d)[4], const uint32_t (&a)[4],
                                          uint32_t b0, uint32_t b1) {
    asm volatile(
        "mma.sync.aligned.m16n8k16.row.col.f32.f16.f16.f32 "
        "{%0,%1,%2,%3}, {%4,%5,%6,%7}, {%8,%9}, {%0,%1,%2,%3};"
        : "+f"(d[0]), "+f"(d[1]), "+f"(d[2]), "+f"(d[3])
        : "r"(a[0]), "r"(a[1]), "r"(a[2]), "r"(a[3]), "r"(b0), "r"(b1));
}

// ---------------- fused pre-pass (exact R11/R15) ----------------
__global__ void k_prepass(const float* __restrict__ x,
                          const int* __restrict__ q,
                          const float* __restrict__ s) {
    __shared__ __half t[128][34];
    int b = blockIdx.x;
    int tid = threadIdx.x;

    if (b < DQ_BLOCKS) {
        int n0 = (b % DQ_BLOCKS_X) * 128;
        int k0 = (b / DQ_BLOCKS_X) * 32;
        int nq = (tid & 31) * 4;
        int kb = tid >> 5;
        int g = k0 >> 6;

        float4 sc4 = *reinterpret_cast<const float4*>(s + (size_t)g * kN + n0 + nq);

#pragma unroll
        for (int p = 0; p < 4; ++p) {
            int k = p * 8 + kb;
            int4 qv = *reinterpret_cast<const int4*>(q + (size_t)(k0 + k) * kN + n0 + nq);
            t[nq + 0][k] = __float2half((float)(qv.x - 8) * sc4.x);
            t[nq + 1][k] = __float2half((float)(qv.y - 8) * sc4.y);
            t[nq + 2][k] = __float2half((float)(qv.z - 8) * sc4.z);
            t[nq + 3][k] = __float2half((float)(qv.w - 8) * sc4.w);
        }
        __syncthreads();

        int n = tid >> 1, seg = tid & 1;
        const uint32_t* src = reinterpret_cast<const uint32_t*>(&t[n][seg * 16]);
        uint32_t r[8];
#pragma unroll
        for (int i = 0; i < 8; ++i) r[i] = src[i];
        float4* dst = reinterpret_cast<float4*>(g_W + (size_t)(n0 + n) * kK + k0 + seg * 16);
        dst[0] = make_float4(__uint_as_float(r[0]), __uint_as_float(r[1]),
                             __uint_as_float(r[2]), __uint_as_float(r[3]));
        dst[1] = make_float4(__uint_as_float(r[4]), __uint_as_float(r[5]),
                             __uint_as_float(r[6]), __uint_as_float(r[7]));
    } else {
        size_t i = (size_t)(b - DQ_BLOCKS) * blockDim.x + tid;
        float4 v0 = reinterpret_cast<const float4*>(x)[2 * i];
        float4 v1 = reinterpret_cast<const float4*>(x)[2 * i + 1];
        __half2 h0 = __floats2half2_rn(v0.x, v0.y);
        __half2 h1 = __floats2half2_rn(v0.z, v0.w);
        __half2 h2 = __floats2half2_rn(v1.x, v1.y);
        __half2 h3 = __floats2half2_rn(v1.z, v1.w);
        float4 o;
        o.x = __uint_as_float(*reinterpret_cast<uint32_t*>(&h0));
        o.y = __uint_as_float(*reinterpret_cast<uint32_t*>(&h1));
        o.z = __uint_as_float(*reinterpret_cast<uint32_t*>(&h2));
        o.w = __uint_as_float(*reinterpret_cast<uint32_t*>(&h3));
        reinterpret_cast<float4*>(g_X)[i] = o;
    }
}

// ---- GEMM: 128x256 tile, TK=128 per stage (2 sub-tiles), 2-stage pipeline --
__global__ void __launch_bounds__(288, 1) k_gemm(
    const __grid_constant__ CUtensorMap tma_a,
    const __grid_constant__ CUtensorMap tma_b,
    float* __restrict__ out)
{
    extern __shared__ char smem[];
    uint32_t sb = smem_u32(smem);
    int tid = threadIdx.x, wid = tid >> 5, lane = tid & 31;
    int tile_m = blockIdx.x % NTM;   // m-fastest: consecutive CTAs share B tiles in L2
    int tile_n = blockIdx.x / NTM;

    if (tid == 0) {
#pragma unroll
        for (int s = 0; s < STAGES; s++) {
            MBARRIER_INIT(sb + OFF_FULL + 8 * s, 1);
            MBARRIER_INIT(sb + OFF_EMPTY + 8 * s, 8);
        }
    }
    __syncthreads();

    if (wid == 8) {
        // ---------------- producer warp: 4 TMA loads per stage ----------------
        if (lane == 0) {
            const int m0 = tile_m * TM;
            const int n0 = tile_n * TN;
#pragma unroll
            for (int s = 0; s < STAGES; s++) {
                MBARRIER_EXPECT_TX(sb + OFF_FULL + 8 * s, STAGE_BYTES);
                uint32_t base = sb + OFF_DATA + s * STAGE_BYTES;
                int kx = s * TK;
                TMA_LOAD_2D(base,                     &tma_a, kx,       m0, sb + OFF_FULL + 8 * s);
                TMA_LOAD_2D(base + SUB_A,             &tma_a, kx + TKB, m0, sb + OFF_FULL + 8 * s);
                TMA_LOAD_2D(base + STAGE_A,           &tma_b, kx,       n0, sb + OFF_FULL + 8 * s);
                TMA_LOAD_2D(base + STAGE_A + SUB_B,   &tma_b, kx + TKB, n0, sb + OFF_FULL + 8 * s);
            }
            for (int it = STAGES; it < KITERS; ++it) {
                int s = it & 1;
                int pe = ((it - 2) >> 1) & 1;
                MBARRIER_WAIT_PARITY(sb + OFF_EMPTY + 8 * s, pe);
                MBARRIER_EXPECT_TX(sb + OFF_FULL + 8 * s, STAGE_BYTES);
                uint32_t base = sb + OFF_DATA + s * STAGE_BYTES;
                int kx = it * TK;
                TMA_LOAD_2D(base,                     &tma_a, kx,       m0, sb + OFF_FULL + 8 * s);
                TMA_LOAD_2D(base + SUB_A,             &tma_a, kx + TKB, m0, sb + OFF_FULL + 8 * s);
                TMA_LOAD_2D(base + STAGE_A,           &tma_b, kx,       n0, sb + OFF_FULL + 8 * s);
                TMA_LOAD_2D(base + STAGE_A + SUB_B,   &tma_b, kx + TKB, n0, sb + OFF_FULL + 8 * s);
            }
        }
        return;
    }

    // ---------------- compute warps (8): each owns a 64x64 sub-tile ----------
    const int warp_m = wid & 1;
    const int warp_n = wid >> 1;
    const uint32_t swz = (uint32_t)(lane & 7) << 4;

    const uint32_t aOff0 = (uint32_t)(warp_m * 64 + (lane & 15)) * 128 + (uint32_t)(lane >> 4) * 16;
    const int grp = lane >> 3;
    const uint32_t bOff0 = (uint32_t)(warp_n * 64 + (grp >> 1) * 8 + (lane & 7)) * 128
                         + (uint32_t)(grp & 1) * 16;

    float acc[4][8][4];
#pragma unroll
    for (int i = 0; i < 4; i++)
#pragma unroll
        for (int j = 0; j < 8; j++)
#pragma unroll
            for (int c = 0; c < 4; c++) acc[i][j][c] = 0.0f;

    for (int it = 0; it < KITERS; ++it) {
        int s = it & 1;
        int pf = (it >> 1) & 1;
        MBARRIER_WAIT_PARITY(sb + OFF_FULL + 8 * s, pf);
        uint32_t sA = sb + OFF_DATA + s * STAGE_BYTES;
        uint32_t sB = sA + STAGE_A;

#pragma unroll
        for (int ks = 0; ks < 8; ++ks) {
            // sub-tile select + intra-sub offset: all compile-time in unrolled loop
            const uint32_t aSub = (uint32_t)(ks >> 2) * SUB_A + (uint32_t)(ks & 3) * 32;
            const uint32_t bSub = (uint32_t)(ks >> 2) * SUB_B + (uint32_t)(ks & 3) * 32;
            uint32_t a_frag[4][4];
            uint32_t b_frag[4][4];
#pragma unroll
            for (int mt = 0; mt < 4; ++mt)
                ldsm_x4(a_frag[mt], (sA + aSub + aOff0 + mt * 2048) ^ swz);
#pragma unroll
            for (int nt2 = 0; nt2 < 4; ++nt2)
                ldsm_x4(b_frag[nt2], (sB + bSub + bOff0 + nt2 * 2048) ^ swz);
#pragma unroll
            for (int mt = 0; mt < 4; ++mt) {
#pragma unroll
                for (int nt2 = 0; nt2 < 4; ++nt2) {
                    mma_16816(acc[mt][2 * nt2 + 0], a_frag[mt], b_frag[nt2][0], b_frag[nt2][1]);
                    mma_16816(acc[mt][2 * nt2 + 1], a_frag[mt], b_frag[nt2][2], b_frag[nt2][3]);
                }
            }
        }
        if (lane == 0) MBARRIER_ARRIVE(sb + OFF_EMPTY + 8 * s);
    }

    // ---------------- epilogue: direct fp32 stores ----------------
    float* dst = out + ((size_t)tile_m * TM) * kN + (size_t)tile_n * TN;
    const int m_off = warp_m * 64 + (lane >> 2);
    const int n_off = warp_n * 64 + (lane & 3) * 2;
#pragma unroll
    for (int mt = 0; mt < 4; ++mt) {
        float* row1 = dst + (size_t)(m_off + mt * 16) * kN + n_off;
        float* row2 = row1 + 8 * (size_t)kN;
#pragma unroll
        for (int nt = 0; nt < 8; ++nt) {
            *reinterpret_cast<float2*>(row1 + nt * 8) = make_float2(acc[mt][nt][0], acc[mt][nt][1]);
            *reinterpret_cast<float2*>(row2 + nt * 8) = make_float2(acc[mt][nt][2], acc[mt][nt][3]);
        }
    }
}

// ---------------- host: tensor maps + launches ----------------
typedef CUresult (CUDAAPI *tmap_encode_fn)(
    CUtensorMap*, CUtensorMapDataType, cuuint32_t, void*,
    const cuuint64_t*, const cuuint64_t*, const cuuint32_t*, const cuuint32_t*,
    CUtensorMapInterleave, CUtensorMapSwizzle, CUtensorMapL2promotion, CUtensorMapFloatOOBfill);

static tmap_encode_fn get_encoder() {
    void* fn = nullptr;
    cudaDriverEntryPointQueryResult st;
    cudaGetDriverEntryPointByVersion("cuTensorMapEncodeTiled", &fn, 12000,
                                     cudaEnableDefault, &st);
    return (tmap_encode_fn)fn;
}

extern "C" void kernel_launch(void* const* d_in, const int* in_sizes, int n_in,
                              void* d_out, int out_size) {
    const float* x = (const float*)d_in[0];
    const int*   q = (const int*)d_in[1];
    const float* s = (const float*)d_in[2];
    float* out = (float*)d_out;

    k_prepass<<<DQ_BLOCKS + CV_BLOCKS, 256>>>(x, q, s);

    void* pX = nullptr; void* pW = nullptr;
    cudaGetSymbolAddress(&pX, g_X);
    cudaGetSymbolAddress(&pW, g_W);
    tmap_encode_fn enc = get_encoder();

    CUtensorMap ta, tb;
    {
        cuuint64_t dims[2]    = {(cuuint64_t)kK, (cuuint64_t)kM};
        cuuint64_t strides[1] = {(cuuint64_t)kK * 2};
        cuuint32_t box[2]     = {(cuuint32_t)TKB, (cuuint32_t)TM};
        cuuint32_t estr[2]    = {1, 1};
        enc(&ta, CU_TENSOR_MAP_DATA_TYPE_FLOAT16, 2, pX, dims, strides, box, estr,
            CU_TENSOR_MAP_INTERLEAVE_NONE, CU_TENSOR_MAP_SWIZZLE_128B,
            CU_TENSOR_MAP_L2_PROMOTION_L2_256B, CU_TENSOR_MAP_FLOAT_OOB_FILL_NONE);
    }
    {
        cuuint64_t dims[2]    = {(cuuint64_t)kK, (cuuint64_t)kN};
        cuuint64_t strides[1] = {(cuuint64_t)kK * 2};
        cuuint32_t box[2]     = {(cuuint32_t)TKB, (cuuint32_t)TN};
        cuuint32_t estr[2]    = {1, 1};
        enc(&tb, CU_TENSOR_MAP_DATA_TYPE_FLOAT16, 2, pW, dims, strides, box, estr,
            CU_TENSOR_MAP_INTERLEAVE_NONE, CU_TENSOR_MAP_SWIZZLE_128B,
            CU_TENSOR_MAP_L2_PROMOTION_L2_256B, CU_TENSOR_MAP_FLOAT_OOB_FILL_NONE);
    }

    cudaFuncSetAttribute(k_gemm, cudaFuncAttributeMaxDynamicSharedMemorySize, SMEM_SIZE);
    k_gemm<<<NTILES, 288, SMEM_SIZE>>>(ta, tb, out);
}